// round 16
// baseline (speedup 1.0000x reference)
#include <cuda_runtime.h>
#include <cuda_fp16.h>
#include <cstdint>

#define B_   8
#define T_   2048
#define HID_ 1024
#define HS_  64
#define NEG_BIG (-3.0e38f)

// scratch (fp16): q [B][T][HS] (pre-scaled), k TRANSPOSED [B][HS][T], v [B][T][HS]
__device__ __half g_q[B_ * T_ * HS_];
__device__ __half g_k[B_ * T_ * HS_];
__device__ __half g_v[B_ * T_ * HS_];

// fp16 W image in the R10-proven swizzled layout:
// [16 ktiles][24576 B] : 64 k-rows x 384 B (192 n x 2B), 16B-XOR swizzled
__device__ __align__(16) uint8_t g_wb[16 * 24576];

// ===========================================================================
// helpers (baseline PTX ISA, compiles for sm_100)
// ===========================================================================
__device__ __forceinline__ uint32_t smem_u32(const void* p) {
    uint32_t a;
    asm("{ .reg .u64 t; cvta.to.shared.u64 t, %1; cvt.u32.u64 %0, t; }" : "=r"(a) : "l"(p));
    return a;
}

#define LDSM_X4(r, addr) \
    asm volatile("ldmatrix.sync.aligned.m8n8.x4.shared.b16 {%0,%1,%2,%3}, [%4];" \
        : "=r"((r)[0]), "=r"((r)[1]), "=r"((r)[2]), "=r"((r)[3]) : "r"(addr))

#define LDSM_X4_T(r, addr) \
    asm volatile("ldmatrix.sync.aligned.m8n8.x4.trans.shared.b16 {%0,%1,%2,%3}, [%4];" \
        : "=r"((r)[0]), "=r"((r)[1]), "=r"((r)[2]), "=r"((r)[3]) : "r"(addr))

#define MMAF16(d, a, b0, b1) \
    asm volatile("mma.sync.aligned.m16n8k16.row.col.f32.f16.f16.f32 " \
        "{%0,%1,%2,%3},{%4,%5,%6,%7},{%8,%9},{%0,%1,%2,%3};" \
        : "+f"((d)[0]), "+f"((d)[1]), "+f"((d)[2]), "+f"((d)[3]) \
        : "r"((a)[0]), "r"((a)[1]), "r"((a)[2]), "r"((a)[3]), "r"(b0), "r"(b1))

#define CPA(dst, src) asm volatile("cp.async.ca.shared.global [%0], [%1], 16;" \
    :: "r"(dst), "l"(__cvta_generic_to_global(src)) : "memory")
#define CPC()  asm volatile("cp.async.commit_group;" ::: "memory")
#define CPW(n) asm volatile("cp.async.wait_group %0;" :: "n"(n) : "memory")

__device__ __forceinline__ uint2 f4_h4(float4 v) {
    __half2 a = __floats2half2_rn(v.x, v.y);
    __half2 b = __floats2half2_rn(v.z, v.w);
    uint2 r;
    r.x = *(uint32_t*)&a;
    r.y = *(uint32_t*)&b;
    return r;
}
__device__ __forceinline__ uint32_t pack_h2(float a, float b) {
    __half2 h = __floats2half2_rn(a, b);
    return *(uint32_t*)&h;
}

// ===========================================================================
// Kernel 0: W -> fp16 swizzled image (R13 verbatim).
// ===========================================================================
__global__ __launch_bounds__(256)
void wprep_kernel(const float* __restrict__ Wq,
                  const float* __restrict__ Wk,
                  const float* __restrict__ Wv)
{
    int idx = blockIdx.x * 256 + threadIdx.x;     // 0..49151 float4s
    int mat = idx >> 14;
    int rem = idx & 16383;
    int k   = rem >> 4;
    int n4  = (rem & 15) << 2;
    const float* W = (mat == 0) ? Wq : (mat == 1) ? Wk : Wv;
    float4 v = *(const float4*)(W + (size_t)k * HS_ + n4);
    uint32_t byte = (uint32_t)((k >> 6) * 24576 + (k & 63) * 384
                  + ((mat * 128 + n4 * 2) ^ ((k & 7) << 4)));
    *(uint2*)(g_wb + byte) = f4_h4(v);
}

// ===========================================================================
// Kernel 1: QKV projection, single-pass fp16 mma m16n8k16 (R13 verbatim).
// ===========================================================================
#define QB_OFF 0
#define QA_OFF 24576
#define QBUFSZ 32768
#define QKV_SMEM 65536

__global__ __launch_bounds__(256, 1)
void qkv_h_kernel(const float* __restrict__ x)
{
    extern __shared__ char sm[];
    const uint32_t sb = smem_u32(sm);

    const int tx   = threadIdx.x;
    const int wid  = tx >> 5;
    const int lane = tx & 31;
    const int row0 = blockIdx.x * 64;

    const int warp_m = wid & 3;
    const int warp_n = wid >> 2;
    const int wr0 = warp_m * 16;
    const int wn0 = warp_n * 96;

    const int a_r    = wr0 + (lane & 7) + ((lane >> 3) & 1) * 8;
    const int a_koff = (lane >> 4) << 3;
    const int a_xr   = (a_r & 7) << 4;

    const int b_k    = (lane & 7) + ((lane >> 3) & 1) * 8;
    const int b_n0   = wn0 + ((lane >> 4) << 3);
    const int b_xr   = (b_k & 7) << 4;

    float acc[12][4] = {};
    float4 px[4];

    // prologue: B(0) via cp.async; A(0) load+cvt+store
    #pragma unroll
    for (int p = 0; p < 6; p++) {
        int ch = tx + 256 * p;
        CPA(sb + QB_OFF + ch * 16, g_wb + ch * 16);
    }
    CPC();
    #pragma unroll
    for (int p = 0; p < 4; p++) {
        int idx = tx + 256 * p;
        px[p] = *(const float4*)(x + (size_t)(row0 + (idx >> 4)) * HID_ + ((idx & 15) << 2));
    }
    #pragma unroll
    for (int p = 0; p < 4; p++) {
        int idx = tx + 256 * p;
        int r = idx >> 4, c4 = (idx & 15) << 2;
        uint32_t byte = (uint32_t)(r * 128 + c4 * 2) ^ ((r & 7) << 4);
        *(uint2*)(sm + QA_OFF + byte) = f4_h4(px[p]);
    }

    for (int kt = 0; kt < 16; kt++) {
        const uint32_t cur = (kt & 1) * QBUFSZ;
        const uint32_t nxt = ((kt + 1) & 1) * QBUFSZ;

        CPW(0);
        __syncthreads();

        if (kt < 15) {
            const uint8_t* src = g_wb + (size_t)(kt + 1) * 24576;
            #pragma unroll
            for (int p = 0; p < 6; p++) {
                int ch = tx + 256 * p;
                CPA(sb + nxt + QB_OFF + ch * 16, src + ch * 16);
            }
            CPC();
            const int k1 = (kt + 1) * 64;
            #pragma unroll
            for (int p = 0; p < 4; p++) {
                int idx = tx + 256 * p;
                px[p] = *(const float4*)(x + (size_t)(row0 + (idx >> 4)) * HID_ + k1 + ((idx & 15) << 2));
            }
        }

        #pragma unroll
        for (int ks = 0; ks < 4; ks++) {
            const int kk = ks * 16 + a_koff;
            const uint32_t aoff = ((uint32_t)(a_r * 128 + kk * 2) ^ a_xr);
            uint32_t ah[4];
            LDSM_X4(ah, sb + cur + QA_OFF + aoff);

            const int bk = ks * 16 + b_k;
            #pragma unroll
            for (int pr = 0; pr < 6; pr++) {
                const int n = b_n0 + pr * 16;
                const uint32_t boff = ((uint32_t)(bk * 384 + n * 2) ^ b_xr);
                uint32_t bh[4];
                LDSM_X4_T(bh, sb + cur + QB_OFF + boff);
                MMAF16(acc[2 * pr],     ah, bh[0], bh[1]);
                MMAF16(acc[2 * pr + 1], ah, bh[2], bh[3]);
            }
        }

        if (kt < 15) {
            #pragma unroll
            for (int p = 0; p < 4; p++) {
                int idx = tx + 256 * p;
                int r = idx >> 4, c4 = (idx & 15) << 2;
                uint32_t byte = ((uint32_t)(r * 128 + c4 * 2) ^ ((r & 7) << 4));
                *(uint2*)(sm + nxt + QA_OFF + byte) = f4_h4(px[p]);
            }
        }
    }

    // epilogue: fp16 stores; q scaled; k transposed [B][HS][T]; v natural
    const int r_lo = row0 + wr0 + (lane >> 2);
    #pragma unroll
    for (int nt = 0; nt < 12; nt++) {
        int nglob = wn0 + nt * 8 + (lane & 3) * 2;
        int mat = nglob >> 6;
        int col = nglob & 63;
        if (mat == 0) {
            const float sc = 0.03125f;
            uint32_t h0 = pack_h2(acc[nt][0] * sc, acc[nt][1] * sc);
            uint32_t h1 = pack_h2(acc[nt][2] * sc, acc[nt][3] * sc);
            *(uint32_t*)(g_q + (size_t)r_lo * HS_ + col)       = h0;
            *(uint32_t*)(g_q + (size_t)(r_lo + 8) * HS_ + col) = h1;
        } else if (mat == 1) {
            int bb = r_lo >> 11, tl = r_lo & 2047;
            __half* dk = g_k + (size_t)bb * HS_ * T_;
            dk[(size_t)col * T_ + tl]           = __float2half_rn(acc[nt][0]);
            dk[(size_t)(col + 1) * T_ + tl]     = __float2half_rn(acc[nt][1]);
            dk[(size_t)col * T_ + tl + 8]       = __float2half_rn(acc[nt][2]);
            dk[(size_t)(col + 1) * T_ + tl + 8] = __float2half_rn(acc[nt][3]);
        } else {
            uint32_t h0 = pack_h2(acc[nt][0], acc[nt][1]);
            uint32_t h1 = pack_h2(acc[nt][2], acc[nt][3]);
            *(uint32_t*)(g_v + (size_t)r_lo * HS_ + col)       = h0;
            *(uint32_t*)(g_v + (size_t)(r_lo + 8) * HS_ + col) = h1;
        }
    }
}

// ===========================================================================
// Kernel 2: causal attention, fp16 mma, FA2 register pipeline + softmax
// SOFTWARE-PIPELINED under the MMAs:
//   iter j:  exp/pack(tile j)  [MUFU, register-local, overlaps barrier]
//            CPW + barrier     [rotation proof identical to R10/13/14]
//            stage KV(j+2)
//            QK(j+1) -> s (overwrites: s dead after pack)   [tensor]
//            PV(j)   <- pa                                  [tensor]
// One barrier/tile; exp fully hidden under 64 back-to-back tensor MMAs.
// Schedule/layout identical to R14 (anti-paired static map, 2 CTAs/SM).
// ===========================================================================
#define KTILE  8192
#define OFF_Q  0
#define OFF_KB 8192
#define OFF_VB 32768
#define ATTN_SMEM 57344

__device__ __forceinline__ void stage_kv2(uint32_t sb, const __half* kh, const __half* vh,
                                          int jj, int pb, int tx)
{
    #pragma unroll
    for (int p = 0; p < 4; p++) {
        int ch = tx + 128 * p;               // 0..511 16B-chunks
        int r = ch >> 3, c = ch & 7;
        uint32_t sw = (uint32_t)(r * 128 + c * 16) ^ ((r & 7) << 4);
        CPA(sb + OFF_KB + pb * KTILE + sw, kh + (size_t)r * T_ + jj + c * 8);
        CPA(sb + OFF_VB + pb * KTILE + sw, vh + (size_t)(jj + r) * HS_ + c * 8);
    }
}

__global__ __launch_bounds__(128, 2)
void attn_h3_kernel(float* __restrict__ out)
{
    extern __shared__ char sm[];
    const uint32_t sb = smem_u32(sm);

    const int tx = threadIdx.x, wid = tx >> 5, lane = tx & 31;
    const int gid = lane >> 2, tig = lane & 3;

    const int bid = blockIdx.x;
    const int t = (bid < 148) ? bid : (403 - bid);   // anti-paired static map
    const int it = 31 - (t >> 3);                    // LPT desc in t
    const int b  = t & 7;
    const int i0 = it * 64;

    const int a_r    = wid * 16 + (lane & 7) + ((lane >> 3) & 1) * 8;
    const int a_koff = (lane >> 4) << 3;
    const int a_xr   = (a_r & 7) << 4;
    const int b_k    = (lane & 7) + ((lane >> 3) & 1) * 8;
    const int b_nb   = (lane >> 4) << 3;
    const int b_xr   = (b_k & 7) << 4;

    const __half* __restrict__ qh = g_q + (size_t)b * T_ * HS_;
    const __half* __restrict__ kh = g_k + (size_t)b * HS_ * T_;
    const __half* __restrict__ vh = g_v + (size_t)b * T_ * HS_;

    // prologue staging: group0 = Q + KV(0); group1 = KV(1) (if present)
    #pragma unroll
    for (int p = 0; p < 4; p++) {
        int ch = tx + 128 * p;
        int r = ch >> 3, c = ch & 7;
        uint32_t sw = (uint32_t)(r * 128 + c * 16) ^ ((r & 7) << 4);
        CPA(sb + OFF_Q + sw, qh + (size_t)(i0 + r) * HS_ + c * 8);
    }
    stage_kv2(sb, kh, vh, 0, 0, tx);
    CPC();
    if (it >= 1) { stage_kv2(sb, kh, vh, 64, 1, tx); CPC(); }

    if (it >= 1) { CPW(1); } else { CPW(0); }   // Q + KV(0) landed
    __syncthreads();

    uint32_t qf[4][4];
    #pragma unroll
    for (int ks = 0; ks < 4; ks++) {
        const int kk = ks * 16 + a_koff;
        LDSM_X4(qf[ks], sb + OFF_Q + ((uint32_t)(a_r * 128 + kk * 2) ^ a_xr));
    }

    float oacc[8][4] = {};
    float l0 = 0.f, l1 = 0.f;
    float s[8][4];

    // QK(0) -> s (buffer 0), mask if it==0
    {
        #pragma unroll
        for (int nf = 0; nf < 8; nf++)
            #pragma unroll
            for (int e = 0; e < 4; e++) s[nf][e] = 0.f;
        const uint32_t Kb = sb + OFF_KB;
        #pragma unroll
        for (int ks = 0; ks < 4; ks++) {
            const int bk = ks * 16 + b_k;
            #pragma unroll
            for (int g = 0; g < 4; g++) {
                const int n = g * 16 + b_nb;
                uint32_t bh[4];
                LDSM_X4_T(bh, Kb + ((uint32_t)(bk * 128 + n * 2) ^ b_xr));
                MMAF16(s[2 * g],     qf[ks], bh[0], bh[1]);
                MMAF16(s[2 * g + 1], qf[ks], bh[2], bh[3]);
            }
        }
        if (it == 0) {
            #pragma unroll
            for (int nf = 0; nf < 8; nf++) {
                const int kk = nf * 8 + tig * 2;
                const int rr = wid * 16 + gid;
                if (kk     > rr)     s[nf][0] = NEG_BIG;
                if (kk + 1 > rr)     s[nf][1] = NEG_BIG;
                if (kk     > rr + 8) s[nf][2] = NEG_BIG;
                if (kk + 1 > rr + 8) s[nf][3] = NEG_BIG;
            }
        }
    }

    for (int j = 0; j <= it; j++) {
        const int bi = j % 3;

        // 1. softmax(tile j): exp + l + pack (registers only; s becomes dead)
        uint32_t pa[4][4];
        #pragma unroll
        for (int nf = 0; nf < 8; nf++) {
            s[nf][0] = __expf(s[nf][0]);
            s[nf][1] = __expf(s[nf][1]);
            s[nf][2] = __expf(s[nf][2]);
            s[nf][3] = __expf(s[nf][3]);
            l0 += s[nf][0] + s[nf][1];
            l1 += s[nf][2] + s[nf][3];
        }
        #pragma unroll
        for (int kc = 0; kc < 4; kc++) {
            pa[kc][0] = pack_h2(s[2 * kc][0],     s[2 * kc][1]);
            pa[kc][1] = pack_h2(s[2 * kc][2],     s[2 * kc][3]);
            pa[kc][2] = pack_h2(s[2 * kc + 1][0], s[2 * kc + 1][1]);
            pa[kc][3] = pack_h2(s[2 * kc + 1][2], s[2 * kc + 1][3]);
        }

        // 2. rotation point: KV(j+1) landed everywhere; buffer (j+2)%3 free
        CPW(0);
        __syncthreads();

        // 3. stage KV(j+2)
        if (j + 2 <= it) { stage_kv2(sb, kh, vh, (j + 2) * 64, (j + 2) % 3, tx); CPC(); }

        // 4. QK(j+1) -> s (overwrite), mask if diagonal
        if (j < it) {
            #pragma unroll
            for (int nf = 0; nf < 8; nf++)
                #pragma unroll
                for (int e = 0; e < 4; e++) s[nf][e] = 0.f;
            const uint32_t Kb = sb + OFF_KB + ((j + 1) % 3) * KTILE;
            #pragma unroll
            for (int ks = 0; ks < 4; ks++) {
                const int bk = ks * 16 + b_k;
                #pragma unroll
                for (int g = 0; g < 4; g++) {
                    const int n = g * 16 + b_nb;
                    uint32_t bh[4];
                    LDSM_X4_T(bh, Kb + ((uint32_t)(bk * 128 + n * 2) ^ b_xr));
                    MMAF16(s[2 * g],     qf[ks], bh[0], bh[1]);
                    MMAF16(s[2 * g + 1], qf[ks], bh[2], bh[3]);
                }
            }
            if (j + 1 == it) {
                #pragma unroll
                for (int nf = 0; nf < 8; nf++) {
                    const int kk = nf * 8 + tig * 2;
                    const int rr = wid * 16 + gid;
                    if (kk     > rr)     s[nf][0] = NEG_BIG;
                    if (kk + 1 > rr)     s[nf][1] = NEG_BIG;
                    if (kk     > rr + 8) s[nf][2] = NEG_BIG;
                    if (kk + 1 > rr + 8) s[nf][3] = NEG_BIG;
                }
            }
        }

        // 5. PV(j) from pa and V(j%3)
        {
            const uint32_t Vb = sb + OFF_VB + bi * KTILE;
            #pragma unroll
            for (int kc = 0; kc < 4; kc++) {
                const int bk = kc * 16 + b_k;
                #pragma unroll
                for (int g = 0; g < 4; g++) {
                    const int n = g * 16 + b_nb;
                    uint32_t bv[4];
                    LDSM_X4_T(bv, Vb + ((uint32_t)(bk * 128 + n * 2) ^ b_xr));
                    MMAF16(oacc[2 * g],     pa[kc], bv[0], bv[1]);
                    MMAF16(oacc[2 * g + 1], pa[kc], bv[2], bv[3]);
                }
            }
        }
    }

    // epilogue: l warp-local (quad reduce), normalize, store fp32
    l0 += __shfl_xor_sync(0xffffffffu, l0, 1);
    l0 += __shfl_xor_sync(0xffffffffu, l0, 2);
    l1 += __shfl_xor_sync(0xffffffffu, l1, 1);
    l1 += __shfl_xor_sync(0xffffffffu, l1, 2);
    const float inv0 = 1.f / l0;
    const float inv1 = 1.f / l1;

    float* ob = out + (size_t)b * T_ * HS_;
    const int r = i0 + wid * 16 + gid;
    #pragma unroll
    for (int nf = 0; nf < 8; nf++) {
        const int h = nf * 8 + tig * 2;
        float2 v0 = { oacc[nf][0] * inv0, oacc[nf][1] * inv0 };
        float2 v1 = { oacc[nf][2] * inv1, oacc[nf][3] * inv1 };
        *(float2*)(ob + (size_t)r * HS_ + h)       = v0;
        *(float2*)(ob + (size_t)(r + 8) * HS_ + h) = v1;
    }
}

// ===========================================================================
extern "C" void kernel_launch(void* const* d_in, const int* in_sizes, int n_in,
                              void* d_out, int out_size)
{
    const float* x  = (const float*)d_in[0];
    const float* Wq = (const float*)d_in[1];
    const float* Wk = (const float*)d_in[2];
    const float* Wv = (const float*)d_in[3];
    float* out = (float*)d_out;

    static bool configured = false;
    if (!configured) {
        cudaFuncSetAttribute(qkv_h_kernel,
                             cudaFuncAttributeMaxDynamicSharedMemorySize, QKV_SMEM);
        cudaFuncSetAttribute(attn_h3_kernel,
                             cudaFuncAttributeMaxDynamicSharedMemorySize, ATTN_SMEM);
        configured = true;
    }

    wprep_kernel<<<192, 256>>>(Wq, Wk, Wv);
    qkv_h_kernel<<<256, 256, QKV_SMEM>>>(x);
    attn_h3_kernel<<<256, 128, ATTN_SMEM>>>(out);
}